// round 1
// baseline (speedup 1.0000x reference)
#include <cuda_runtime.h>

#define TILE 128
#define KT 16
#define NTHREADS 256

static constexpr int NB  = 2;     // batch
static constexpr int S   = 4096;  // 64*64 spatial
static constexpr int CIN = 2048;
static constexpr int RC  = 512;
static constexpr int OC  = 4096;
static constexpr float BN_EPS = 1e-5f;
static constexpr int KCH = 8;           // k-chunks for softmax stats
static constexpr int KSEG = S / KCH;    // 512 rows per chunk

// ---------------- device scratch (static: no allocations allowed) ----------
__device__ float g_red[(size_t)NB * RC * S];            // 16.8 MB
__device__ float g_h  [(size_t)NB * RC * S];            // 16.8 MB
__device__ float g_a  [(size_t)NB * OC * S];            // 134 MB
__device__ float g_m  [NB * S];
__device__ float g_z  [NB * S];
__device__ float g_pm [KCH * NB * S];
__device__ float g_pz [KCH * NB * S];

// ---------------- helpers ---------------------------------------------------
__device__ __forceinline__ void fma2(unsigned long long& d,
                                     unsigned long long a,
                                     unsigned long long b) {
    asm("fma.rn.f32x2 %0, %1, %2, %0;" : "+l"(d) : "l"(a), "l"(b));
}

__device__ __forceinline__ unsigned long long dup2(float v) {
    unsigned long long r;
    asm("mov.b64 %0, {%1, %1};" : "=l"(r) : "f"(v));
    return r;
}

union F2U { unsigned long long u; float2 f; };

// ---------------- generic tiled GEMM: C[M,N] = A[M,K] * B[K,N] --------------
// EP: 0 = none, 1 = BN+ReLU (bn is [4,M]), 2 = divide column sum (zcol [N] per batch)
enum { EP_NONE = 0, EP_BNRELU = 1, EP_SOFTDIV = 2 };

template <int EP>
__global__ __launch_bounds__(NTHREADS, 2)
void gemm_kernel(const float* __restrict__ A, const float* __restrict__ B,
                 float* __restrict__ Cm,
                 int M, int K, int N,
                 size_t aBS, size_t bBS, size_t cBS,
                 const float* __restrict__ bnp,
                 const float* __restrict__ zcol)
{
    __shared__ __align__(16) unsigned long long As[KT][TILE]; // A duplicated (v,v) pairs
    __shared__ __align__(16) float Bs[KT][TILE];

    const int bz = blockIdx.z;
    A  += (size_t)bz * aBS;
    B  += (size_t)bz * bBS;
    Cm += (size_t)bz * cBS;

    const int m0 = blockIdx.y * TILE;
    const int n0 = blockIdx.x * TILE;
    const int t  = threadIdx.x;
    const int tx = t & 15;
    const int ty = t >> 4;

    const float* Ab = A + (size_t)m0 * K;
    const float* Bb = B + n0;

    unsigned long long acc[8][4];
#pragma unroll
    for (int i = 0; i < 8; i++)
#pragma unroll
        for (int j = 0; j < 4; j++) acc[i][j] = 0ull;

    // global-load index plan: q = i*256 + t  (contiguous warps -> full 128B lines)
    const int a_row0 = t >> 2;            // 0..63
    const int a_kc   = (t & 3) * 4;       // 0,4,8,12
    const int b_row0 = t >> 5;            // 0..7
    const int b_col  = (t & 31) * 4;      // 0..124

    float4 pa0, pa1, pb0, pb1;

#define LOAD_TILES(k0)                                                          \
    do {                                                                        \
        pa0 = *reinterpret_cast<const float4*>(Ab + (size_t)a_row0 * K + (k0) + a_kc);        \
        pa1 = *reinterpret_cast<const float4*>(Ab + (size_t)(a_row0 + 64) * K + (k0) + a_kc); \
        pb0 = *reinterpret_cast<const float4*>(Bb + (size_t)((k0) + b_row0) * N + b_col);     \
        pb1 = *reinterpret_cast<const float4*>(Bb + (size_t)((k0) + b_row0 + 8) * N + b_col); \
    } while (0)

    LOAD_TILES(0);

    for (int k0 = 0; k0 < K; k0 += KT) {
        // stage regs -> smem (A duplicated into f32x2 pairs)
        As[a_kc + 0][a_row0] = dup2(pa0.x);
        As[a_kc + 1][a_row0] = dup2(pa0.y);
        As[a_kc + 2][a_row0] = dup2(pa0.z);
        As[a_kc + 3][a_row0] = dup2(pa0.w);
        As[a_kc + 0][a_row0 + 64] = dup2(pa1.x);
        As[a_kc + 1][a_row0 + 64] = dup2(pa1.y);
        As[a_kc + 2][a_row0 + 64] = dup2(pa1.z);
        As[a_kc + 3][a_row0 + 64] = dup2(pa1.w);
        *reinterpret_cast<float4*>(&Bs[b_row0][b_col])     = pb0;
        *reinterpret_cast<float4*>(&Bs[b_row0 + 8][b_col]) = pb1;
        __syncthreads();

        if (k0 + KT < K) LOAD_TILES(k0 + KT);

#pragma unroll
        for (int kt = 0; kt < KT; kt++) {
            ulonglong2 a01 = *reinterpret_cast<const ulonglong2*>(&As[kt][ty * 4]);
            ulonglong2 a23 = *reinterpret_cast<const ulonglong2*>(&As[kt][ty * 4 + 2]);
            ulonglong2 a45 = *reinterpret_cast<const ulonglong2*>(&As[kt][64 + ty * 4]);
            ulonglong2 a67 = *reinterpret_cast<const ulonglong2*>(&As[kt][64 + ty * 4 + 2]);
            ulonglong2 b01 = *reinterpret_cast<const ulonglong2*>(&Bs[kt][tx * 4]);
            ulonglong2 b23 = *reinterpret_cast<const ulonglong2*>(&Bs[kt][64 + tx * 4]);
            unsigned long long av[8] = {a01.x, a01.y, a23.x, a23.y,
                                        a45.x, a45.y, a67.x, a67.y};
            unsigned long long bv[4] = {b01.x, b01.y, b23.x, b23.y};
#pragma unroll
            for (int i = 0; i < 8; i++)
#pragma unroll
                for (int j = 0; j < 4; j++)
                    fma2(acc[i][j], av[i], bv[j]);
        }
        __syncthreads();
    }
#undef LOAD_TILES

    // ---------------- epilogue ----------------
    float zc[8];
    if (EP == EP_SOFTDIV) {
        const float* zb = zcol + (size_t)bz * N + n0;
        float4 z0 = *reinterpret_cast<const float4*>(zb + tx * 4);
        float4 z1 = *reinterpret_cast<const float4*>(zb + 64 + tx * 4);
        zc[0] = z0.x; zc[1] = z0.y; zc[2] = z0.z; zc[3] = z0.w;
        zc[4] = z1.x; zc[5] = z1.y; zc[6] = z1.z; zc[7] = z1.w;
    }

#pragma unroll
    for (int ii = 0; ii < 8; ii++) {
        const int rr = (ii < 4) ? (ty * 4 + ii) : (64 + ty * 4 + (ii - 4));
        const int r  = m0 + rr;
        float scale = 1.f, shift = 0.f;
        if (EP == EP_BNRELU) {
            float g  = bnp[r];
            float be = bnp[M + r];
            float mu = bnp[2 * M + r];
            float va = bnp[3 * M + r];
            scale = g * rsqrtf(va + BN_EPS);
            shift = be - mu * scale;
        }
        float o[8];
#pragma unroll
        for (int j = 0; j < 4; j++) {
            F2U u; u.u = acc[ii][j];
            o[2 * j]     = u.f.x;
            o[2 * j + 1] = u.f.y;
        }
        if (EP == EP_BNRELU) {
#pragma unroll
            for (int j = 0; j < 8; j++) o[j] = fmaxf(o[j] * scale + shift, 0.f);
        }
        if (EP == EP_SOFTDIV) {
#pragma unroll
            for (int j = 0; j < 8; j++) o[j] = o[j] / zc[j];
        }
        float* Crow = Cm + (size_t)r * N + n0;
        *reinterpret_cast<float4*>(Crow + tx * 4)      = make_float4(o[0], o[1], o[2], o[3]);
        *reinterpret_cast<float4*>(Crow + 64 + tx * 4) = make_float4(o[4], o[5], o[6], o[7]);
    }
}

// -------- softmax stats: deterministic two-stage (no float atomics) ---------
__global__ void colmax_part(const float* __restrict__ a, float* __restrict__ pm)
{
    const int n  = blockIdx.z;
    const int tc = blockIdx.x * blockDim.x + threadIdx.x;
    const int kc = blockIdx.y;
    const float* p = a + (size_t)n * S * S + (size_t)kc * KSEG * S + tc;
    float mx = -3.402823466e38f;
#pragma unroll 8
    for (int k = 0; k < KSEG; k++)
        mx = fmaxf(mx, p[(size_t)k * S]);
    pm[(size_t)kc * (NB * S) + n * S + tc] = mx;
}

template <bool IS_MAX>
__global__ void reduce_parts(const float* __restrict__ part, float* __restrict__ outv)
{
    const int i = blockIdx.x * blockDim.x + threadIdx.x;
    if (i >= NB * S) return;
    float v = IS_MAX ? -3.402823466e38f : 0.f;
#pragma unroll
    for (int c = 0; c < KCH; c++) {
        float p = part[(size_t)c * (NB * S) + i];
        v = IS_MAX ? fmaxf(v, p) : (v + p);
    }
    outv[i] = v;
}

__global__ void expsum_part(float* __restrict__ a, const float* __restrict__ m,
                            float* __restrict__ pz)
{
    const int n  = blockIdx.z;
    const int tc = blockIdx.x * blockDim.x + threadIdx.x;
    const int kc = blockIdx.y;
    const float mv = m[n * S + tc];
    float* p = a + (size_t)n * S * S + (size_t)kc * KSEG * S + tc;
    float s = 0.f;
#pragma unroll 8
    for (int k = 0; k < KSEG; k++) {
        float v = __expf(p[(size_t)k * S] - mv);
        p[(size_t)k * S] = v;
        s += v;
    }
    pz[(size_t)kc * (NB * S) + n * S + tc] = s;
}

// ---------------- launch ----------------------------------------------------
extern "C" void kernel_launch(void* const* d_in, const int* in_sizes, int n_in,
                              void* d_out, int out_size)
{
    (void)in_sizes; (void)n_in; (void)out_size;
    const float* x = (const float*)d_in[0];
    float* out = (float*)d_out;

    float *pred, *ph, *pa, *pm, *pz, *ppm, *ppz;
    cudaGetSymbolAddress((void**)&pred, g_red);
    cudaGetSymbolAddress((void**)&ph,   g_h);
    cudaGetSymbolAddress((void**)&pa,   g_a);
    cudaGetSymbolAddress((void**)&pm,   g_m);
    cudaGetSymbolAddress((void**)&pz,   g_z);
    cudaGetSymbolAddress((void**)&ppm,  g_pm);
    cudaGetSymbolAddress((void**)&ppz,  g_pz);

    const dim3 blk(NTHREADS);

    for (int br = 0; br < 2; br++) {
        const float* wred = (const float*)d_in[1 + br * 5 + 0];
        const float* bn1  = (const float*)d_in[1 + br * 5 + 1];
        const float* w1   = (const float*)d_in[1 + br * 5 + 2];
        const float* bn2  = (const float*)d_in[1 + br * 5 + 3];
        const float* w2   = (const float*)d_in[1 + br * 5 + 4];

        // red = relu(bn1(w_red @ x))  : [NB,512,4096]
        gemm_kernel<EP_BNRELU><<<dim3(S / TILE, RC / TILE, NB), blk>>>(
            wred, x, pred, RC, CIN, S,
            0, (size_t)CIN * S, (size_t)RC * S, bn1, nullptr);

        // h = relu(bn2(w1 @ red))    : [NB,512,4096]
        gemm_kernel<EP_BNRELU><<<dim3(S / TILE, RC / TILE, NB), blk>>>(
            w1, pred, ph, RC, RC, S,
            0, (size_t)RC * S, (size_t)RC * S, bn2, nullptr);

        // a = w2 @ h                 : [NB,4096,4096]
        gemm_kernel<EP_NONE><<<dim3(S / TILE, OC / TILE, NB), blk>>>(
            w2, ph, pa, OC, RC, S,
            0, (size_t)RC * S, (size_t)OC * S, nullptr, nullptr);

        // column softmax stats (deterministic)
        colmax_part<<<dim3(S / 256, KCH, NB), 256>>>(pa, ppm);
        reduce_parts<true><<<(NB * S + 255) / 256, 256>>>(ppm, pm);
        expsum_part<<<dim3(S / 256, KCH, NB), 256>>>(pa, pm, ppz);
        reduce_parts<false><<<(NB * S + 255) / 256, 256>>>(ppz, pz);

        // fm = red @ exp(a-m) / Z    : -> out[n][br*512 .. br*512+511][:]
        gemm_kernel<EP_SOFTDIV><<<dim3(S / TILE, RC / TILE, NB), blk>>>(
            pred, pa, out + (size_t)br * RC * S, RC, S, S,
            (size_t)RC * S, (size_t)OC * S, (size_t)2 * RC * S,
            nullptr, pz);
    }
}

// round 3
// speedup vs baseline: 2.2611x; 2.2611x over previous
#include <cuda_runtime.h>
#include <cuda_bf16.h>
#include <cstdint>

static constexpr int NB  = 2;
static constexpr int S   = 4096;
static constexpr int CIN = 2048;
static constexpr int RC  = 512;
static constexpr int OC  = 4096;
static constexpr int KCH  = 8;
static constexpr int KSEG = S / KCH;

// ---------------- device scratch (bf16 hi/lo planes) ------------------------
__device__ __align__(16) __nv_bfloat16 g_xh [(size_t)NB * CIN * S];
__device__ __align__(16) __nv_bfloat16 g_xl [(size_t)NB * CIN * S];
__device__ __align__(16) __nv_bfloat16 g_wrh[(size_t)RC * CIN];
__device__ __align__(16) __nv_bfloat16 g_wrl[(size_t)RC * CIN];
__device__ __align__(16) __nv_bfloat16 g_w1h[(size_t)RC * RC];
__device__ __align__(16) __nv_bfloat16 g_w1l[(size_t)RC * RC];
__device__ __align__(16) __nv_bfloat16 g_w2h[(size_t)OC * RC];
__device__ __align__(16) __nv_bfloat16 g_w2l[(size_t)OC * RC];
__device__ __align__(16) __nv_bfloat16 g_redh[(size_t)NB * RC * S];
__device__ __align__(16) __nv_bfloat16 g_redl[(size_t)NB * RC * S];
__device__ __align__(16) __nv_bfloat16 g_hh [(size_t)NB * RC * S];
__device__ __align__(16) __nv_bfloat16 g_hl [(size_t)NB * RC * S];
__device__ __align__(16) __nv_bfloat16 g_ah [(size_t)NB * OC * S];
__device__ __align__(16) __nv_bfloat16 g_al [(size_t)NB * OC * S];
__device__ float g_m [NB * S];
__device__ float g_z [NB * S];
__device__ float g_pm[KCH * NB * S];
__device__ float g_pz[KCH * NB * S];

// ---------------- helpers ----------------------------------------------------
#define SW(o) ((o) ^ (((o) >> 3) & 0x70))

__device__ __forceinline__ uint32_t s2u(const void* p) {
    uint32_t a;
    asm("{ .reg .u64 t; cvta.to.shared.u64 t, %1; cvt.u32.u64 %0, t; }"
        : "=r"(a) : "l"(p));
    return a;
}

__device__ __forceinline__ void cpa16(uint32_t s, const void* g) {
    asm volatile("cp.async.cg.shared.global [%0], [%1], 16;" :: "r"(s), "l"(g));
}

#define CP_COMMIT() asm volatile("cp.async.commit_group;" ::: "memory")
#define CP_WAIT0()  asm volatile("cp.async.wait_group 0;" ::: "memory")

#define LDSM4(r, a)                                                            \
    asm volatile("ldmatrix.sync.aligned.m8n8.x4.shared.b16 {%0,%1,%2,%3}, [%4];" \
                 : "=r"((r)[0]), "=r"((r)[1]), "=r"((r)[2]), "=r"((r)[3])      \
                 : "r"(a))

#define LDSM2T(r, a)                                                           \
    asm volatile("ldmatrix.sync.aligned.m8n8.x2.trans.shared.b16 {%0,%1}, [%2];" \
                 : "=r"((r)[0]), "=r"((r)[1]) : "r"(a))

__device__ __forceinline__ void mma16816(float* d, const uint32_t* a,
                                         const uint32_t* b) {
    asm volatile(
        "mma.sync.aligned.m16n8k16.row.col.f32.bf16.bf16.f32 "
        "{%0,%1,%2,%3}, {%4,%5,%6,%7}, {%8,%9}, {%0,%1,%2,%3};"
        : "+f"(d[0]), "+f"(d[1]), "+f"(d[2]), "+f"(d[3])
        : "r"(a[0]), "r"(a[1]), "r"(a[2]), "r"(a[3]), "r"(b[0]), "r"(b[1]));
}

// split fp32 pair into packed bf16 hi plane + lo plane
__device__ __forceinline__ void split2(float a, float b, uint32_t& h, uint32_t& l) {
    uint32_t hh;
    asm("cvt.rn.bf16x2.f32 %0, %1, %2;" : "=r"(hh) : "f"(b), "f"(a));
    float ah = __uint_as_float(hh << 16);
    float bh = __uint_as_float(hh & 0xffff0000u);
    float ar = a - ah;
    float br = b - bh;
    asm("cvt.rn.bf16x2.f32 %0, %1, %2;" : "=r"(l) : "f"(br), "f"(ar));
    h = hh;
}

// SMEM layout: 2 stages x (AHI 16K | ALO 16K | BHI 16K | BLO 16K)
static constexpr int STG    = 65536;
static constexpr int OFF_AHI = 0;
static constexpr int OFF_ALO = 16384;
static constexpr int OFF_BHI = 32768;
static constexpr int OFF_BLO = 49152;
static constexpr int SMEM_BYTES = 2 * STG;   // 131072

enum { EPL_BNRELU = 0, EPL_PLAIN = 1, EPF_DIV = 2 };

// ============== split-bf16 tensor GEMM: C = (Ahi+Alo)(Bhi+Blo) ===============
template <int EP>
__global__ void __launch_bounds__(256, 1)
gemm_mma(const __nv_bfloat16* __restrict__ Ahi, const __nv_bfloat16* __restrict__ Alo,
         const __nv_bfloat16* __restrict__ Bhi, const __nv_bfloat16* __restrict__ Blo,
         float* __restrict__ Cf,
         __nv_bfloat16* __restrict__ Chi, __nv_bfloat16* __restrict__ Clo,
         int M, int K, int N,
         size_t aBS, size_t bBS, size_t cBS,
         const float* __restrict__ bnp, const float* __restrict__ zcol)
{
    extern __shared__ char smem[];
    const uint32_t sb = s2u(smem);
    const int t = threadIdx.x, wid = t >> 5, lane = t & 31;
    const int bz = blockIdx.z;
    const int m0 = blockIdx.y * 128, n0 = blockIdx.x * 128;
    const int wm0 = (wid >> 2) * 64, wn0 = (wid & 3) * 32;

    const __nv_bfloat16* Abh = Ahi + bz * aBS + (size_t)m0 * K;
    const __nv_bfloat16* Abl = Alo + bz * aBS + (size_t)m0 * K;
    const __nv_bfloat16* Bbh = Bhi + bz * bBS + n0;
    const __nv_bfloat16* Bbl = Blo + bz * bBS + n0;

    // per-thread load plan
    const int a_r = t >> 3, a_c = t & 7;              // A: rows a_r+32*it, 16B chunk a_c
    const int b_k = t >> 4, b_h = (t >> 3) & 1, b_c = t & 7;

    auto load_chunk = [&](int k0, int buf) {
        const uint32_t st = sb + buf * STG;
#pragma unroll
        for (int it = 0; it < 4; it++) {
            int row = it * 32 + a_r;
            uint32_t d = (uint32_t)SW(row * 128 + a_c * 16);
            size_t so = (size_t)row * K + k0 + a_c * 8;
            cpa16(st + OFF_AHI + d, Abh + so);
            cpa16(st + OFF_ALO + d, Abl + so);
        }
#pragma unroll
        for (int it = 0; it < 4; it++) {
            int k = it * 16 + b_k;
            uint32_t d = (uint32_t)(b_h * 8192 + SW(k * 128 + b_c * 16));
            size_t so = (size_t)(k0 + k) * N + b_h * 64 + b_c * 8;
            cpa16(st + OFF_BHI + d, Bbh + so);
            cpa16(st + OFF_BLO + d, Bbl + so);
        }
        CP_COMMIT();
    };

    float acc[4][4][4];
#pragma unroll
    for (int i = 0; i < 4; i++)
#pragma unroll
        for (int j = 0; j < 4; j++)
#pragma unroll
            for (int q = 0; q < 4; q++) acc[i][j][q] = 0.f;

    // ldmatrix per-lane address components
    const int la_row = lane & 15;            // A: row within 16, and B: k within 16
    const int la_kc  = (lane >> 4) * 8;      // A: k chunk select

    load_chunk(0, 0);

    const int nc = K / 64;
    for (int ci = 0; ci < nc; ci++) {
        const int buf = ci & 1;
        CP_WAIT0();
        __syncthreads();
        if (ci + 1 < nc) load_chunk((ci + 1) * 64, buf ^ 1);

        const uint32_t st = sb + buf * STG;
#pragma unroll
        for (int ks = 0; ks < 4; ks++) {
            uint32_t ahi[4][4], alo[4][4], bhi[4][2], blo[4][2];
#pragma unroll
            for (int i = 0; i < 4; i++) {
                uint32_t d = (uint32_t)SW((wm0 + 16 * i + la_row) * 128 +
                                          (ks * 16 + la_kc) * 2);
                LDSM4(ahi[i], st + OFF_AHI + d);
                LDSM4(alo[i], st + OFF_ALO + d);
            }
#pragma unroll
            for (int j = 0; j < 4; j++) {
                int col = wn0 + 8 * j;
                uint32_t d = (uint32_t)((col >> 6) * 8192 +
                                        SW((ks * 16 + la_row) * 128 + (col & 63) * 2));
                LDSM2T(bhi[j], st + OFF_BHI + d);
                LDSM2T(blo[j], st + OFF_BLO + d);
            }
#pragma unroll
            for (int i = 0; i < 4; i++)
#pragma unroll
                for (int j = 0; j < 4; j++) {
                    mma16816(acc[i][j], ahi[i], bhi[j]);
                    mma16816(acc[i][j], ahi[i], blo[j]);
                    mma16816(acc[i][j], alo[i], bhi[j]);
                }
        }
        __syncthreads();
    }

    // ---------------- epilogue ----------------
    const int g  = lane >> 2;
    const int t2 = lane & 3;

#pragma unroll
    for (int i = 0; i < 4; i++) {
        const int r0 = m0 + wm0 + 16 * i + g;
        const int r1 = r0 + 8;
        float sc0 = 1.f, sh0 = 0.f, sc1 = 1.f, sh1 = 0.f;
        if (EP == EPL_BNRELU) {
            float ga = bnp[r0], be = bnp[M + r0], mu = bnp[2 * M + r0], va = bnp[3 * M + r0];
            sc0 = ga * rsqrtf(va + 1e-5f);
            sh0 = be - mu * sc0;
            ga = bnp[r1]; be = bnp[M + r1]; mu = bnp[2 * M + r1]; va = bnp[3 * M + r1];
            sc1 = ga * rsqrtf(va + 1e-5f);
            sh1 = be - mu * sc1;
        }
#pragma unroll
        for (int j = 0; j < 4; j++) {
            const int c = n0 + wn0 + 8 * j + t2 * 2;
            float v0 = acc[i][j][0], v1 = acc[i][j][1];
            float v2 = acc[i][j][2], v3 = acc[i][j][3];
            if (EP == EPL_BNRELU) {
                v0 = fmaxf(v0 * sc0 + sh0, 0.f);
                v1 = fmaxf(v1 * sc0 + sh0, 0.f);
                v2 = fmaxf(v2 * sc1 + sh1, 0.f);
                v3 = fmaxf(v3 * sc1 + sh1, 0.f);
            }
            if (EP == EPF_DIV) {
                const float* zb = zcol + (size_t)bz * N + c;
                float z0 = zb[0], z1 = zb[1];
                float2* Cr0 = (float2*)(Cf + bz * cBS + (size_t)r0 * N + c);
                float2* Cr1 = (float2*)(Cf + bz * cBS + (size_t)r1 * N + c);
                *Cr0 = make_float2(v0 / z0, v1 / z1);
                *Cr1 = make_float2(v2 / z0, v3 / z1);
            } else {
                uint32_t h0, l0, h1, l1;
                split2(v0, v1, h0, l0);
                split2(v2, v3, h1, l1);
                size_t cb0 = bz * cBS + (size_t)r0 * N + c;
                size_t cb1 = bz * cBS + (size_t)r1 * N + c;
                *(uint32_t*)(Chi + cb0) = h0;
                *(uint32_t*)(Clo + cb0) = l0;
                *(uint32_t*)(Chi + cb1) = h1;
                *(uint32_t*)(Clo + cb1) = l1;
            }
        }
    }
}

// ================= fp32 -> bf16 hi/lo plane conversion ======================
__global__ void to_planes(const float4* __restrict__ src,
                          uint2* __restrict__ hi, uint2* __restrict__ lo, int n4)
{
    int i = blockIdx.x * blockDim.x + threadIdx.x;
    if (i >= n4) return;
    float4 f = src[i];
    uint2 h, l;
    split2(f.x, f.y, h.x, l.x);
    split2(f.z, f.w, h.y, l.y);
    hi[i] = h;
    lo[i] = l;
}

// ================= softmax stats over a-planes ==============================
__global__ void colmax_part(const __nv_bfloat16* __restrict__ ah, float* __restrict__ pm)
{
    const int n  = blockIdx.z;
    const int tc = blockIdx.x * blockDim.x + threadIdx.x;
    const int kc = blockIdx.y;
    const __nv_bfloat16* p = ah + (size_t)n * S * S + (size_t)kc * KSEG * S + tc;
    float mx = -3.402823466e38f;
#pragma unroll 8
    for (int k = 0; k < KSEG; k++)
        mx = fmaxf(mx, __bfloat162float(p[(size_t)k * S]));
    pm[(size_t)kc * (NB * S) + n * S + tc] = mx;
}

template <bool IS_MAX>
__global__ void reduce_parts(const float* __restrict__ part, float* __restrict__ outv)
{
    const int i = blockIdx.x * blockDim.x + threadIdx.x;
    if (i >= NB * S) return;
    float v = IS_MAX ? -3.402823466e38f : 0.f;
#pragma unroll
    for (int c = 0; c < KCH; c++) {
        float p = part[(size_t)c * (NB * S) + i];
        v = IS_MAX ? fmaxf(v, p) : (v + p);
    }
    outv[i] = v;
}

__global__ void expsum_part(__nv_bfloat16* __restrict__ ah, __nv_bfloat16* __restrict__ al,
                            const float* __restrict__ m, float* __restrict__ pz)
{
    const int n  = blockIdx.z;
    const int tc = blockIdx.x * blockDim.x + threadIdx.x;
    const int kc = blockIdx.y;
    const float mv = m[n * S + tc];
    const size_t base = (size_t)n * S * S + (size_t)kc * KSEG * S + tc;
    float s = 0.f;
#pragma unroll 4
    for (int k = 0; k < KSEG; k++) {
        size_t idx = base + (size_t)k * S;
        float f = __bfloat162float(ah[idx]) + __bfloat162float(al[idx]);
        float v = __expf(f - mv);
        s += v;
        __nv_bfloat16 vh = __float2bfloat16(v);
        float vr = v - __bfloat162float(vh);
        ah[idx] = vh;
        al[idx] = __float2bfloat16(vr);
    }
    pz[(size_t)kc * (NB * S) + n * S + tc] = s;
}

// ================= launch ====================================================
extern "C" void kernel_launch(void* const* d_in, const int* in_sizes, int n_in,
                              void* d_out, int out_size)
{
    (void)in_sizes; (void)n_in; (void)out_size;
    const float* x = (const float*)d_in[0];
    float* out = (float*)d_out;

    __nv_bfloat16 *xh, *xl, *wrh, *wrl, *w1h, *w1l, *w2h, *w2l;
    __nv_bfloat16 *redh, *redl, *hh, *hl, *ah, *al;
    float *m_, *z_, *pm_, *pz_;
    cudaGetSymbolAddress((void**)&xh, g_xh);   cudaGetSymbolAddress((void**)&xl, g_xl);
    cudaGetSymbolAddress((void**)&wrh, g_wrh); cudaGetSymbolAddress((void**)&wrl, g_wrl);
    cudaGetSymbolAddress((void**)&w1h, g_w1h); cudaGetSymbolAddress((void**)&w1l, g_w1l);
    cudaGetSymbolAddress((void**)&w2h, g_w2h); cudaGetSymbolAddress((void**)&w2l, g_w2l);
    cudaGetSymbolAddress((void**)&redh, g_redh); cudaGetSymbolAddress((void**)&redl, g_redl);
    cudaGetSymbolAddress((void**)&hh, g_hh);   cudaGetSymbolAddress((void**)&hl, g_hl);
    cudaGetSymbolAddress((void**)&ah, g_ah);   cudaGetSymbolAddress((void**)&al, g_al);
    cudaGetSymbolAddress((void**)&m_, g_m);    cudaGetSymbolAddress((void**)&z_, g_z);
    cudaGetSymbolAddress((void**)&pm_, g_pm);  cudaGetSymbolAddress((void**)&pz_, g_pz);

    cudaFuncSetAttribute(gemm_mma<EPL_BNRELU>, cudaFuncAttributeMaxDynamicSharedMemorySize, SMEM_BYTES);
    cudaFuncSetAttribute(gemm_mma<EPL_PLAIN>,  cudaFuncAttributeMaxDynamicSharedMemorySize, SMEM_BYTES);
    cudaFuncSetAttribute(gemm_mma<EPF_DIV>,    cudaFuncAttributeMaxDynamicSharedMemorySize, SMEM_BYTES);

    // x -> planes (once per call)
    {
        int n4 = NB * CIN * S / 4;
        to_planes<<<(n4 + 255) / 256, 256>>>((const float4*)x, (uint2*)xh, (uint2*)xl, n4);
    }

    for (int br = 0; br < 2; br++) {
        const float* wred = (const float*)d_in[1 + br * 5 + 0];
        const float* bn1  = (const float*)d_in[1 + br * 5 + 1];
        const float* w1   = (const float*)d_in[1 + br * 5 + 2];
        const float* bn2  = (const float*)d_in[1 + br * 5 + 3];
        const float* w2   = (const float*)d_in[1 + br * 5 + 4];

        {
            int n4 = RC * CIN / 4;
            to_planes<<<(n4 + 255) / 256, 256>>>((const float4*)wred, (uint2*)wrh, (uint2*)wrl, n4);
            n4 = RC * RC / 4;
            to_planes<<<(n4 + 255) / 256, 256>>>((const float4*)w1, (uint2*)w1h, (uint2*)w1l, n4);
            n4 = OC * RC / 4;
            to_planes<<<(n4 + 255) / 256, 256>>>((const float4*)w2, (uint2*)w2h, (uint2*)w2l, n4);
        }

        // red = relu(bn1(wred @ x))  -> planes
        gemm_mma<EPL_BNRELU><<<dim3(S / 128, RC / 128, NB), 256, SMEM_BYTES>>>(
            wrh, wrl, xh, xl, nullptr, redh, redl,
            RC, CIN, S, 0, (size_t)CIN * S, (size_t)RC * S, bn1, nullptr);

        // h = relu(bn2(w1 @ red))   -> planes
        gemm_mma<EPL_BNRELU><<<dim3(S / 128, RC / 128, NB), 256, SMEM_BYTES>>>(
            w1h, w1l, redh, redl, nullptr, hh, hl,
            RC, RC, S, 0, (size_t)RC * S, (size_t)RC * S, bn2, nullptr);

        // a = w2 @ h                -> planes
        gemm_mma<EPL_PLAIN><<<dim3(S / 128, OC / 128, NB), 256, SMEM_BYTES>>>(
            w2h, w2l, hh, hl, nullptr, ah, al,
            OC, RC, S, 0, (size_t)RC * S, (size_t)OC * S, nullptr, nullptr);

        // deterministic column softmax, exp in place
        colmax_part<<<dim3(S / 256, KCH, NB), 256>>>(ah, pm_);
        reduce_parts<true><<<(NB * S + 255) / 256, 256>>>(pm_, m_);
        expsum_part<<<dim3(S / 256, KCH, NB), 256>>>(ah, al, m_, pz_);
        reduce_parts<false><<<(NB * S + 255) / 256, 256>>>(pz_, z_);

        // fm = red @ exp(a-m) / Z   -> fp32 out slice
        gemm_mma<EPF_DIV><<<dim3(S / 128, RC / 128, NB), 256, SMEM_BYTES>>>(
            redh, redl, ah, al, out + (size_t)br * RC * S, nullptr, nullptr,
            RC, S, S, (size_t)RC * S, (size_t)S * S, (size_t)2 * RC * S,
            nullptr, z_);
    }
}